// round 12
// baseline (speedup 1.0000x reference)
#include <cuda_runtime.h>
#include <cstdint>

// Problem constants
#define B_   1024
#define T_   512
#define I_   16
#define H_   50
#define G_   200      // 4*H
#define FCD  64
#define NB   7        // rows per block -> grid 147, single wave
#define NTH  384      // 12 warps: 6 sections x 64 threads (50 active each)
#define NC1  (NB * H_)        // 350
#define NCELL (2 * NB * H_)   // 700

typedef unsigned long long ull;

// Precomputed bias-folded x-gates for layer 1: [t][b][g] (g = cls*50 + j).
// Padding covers the boundary block's over-read (rows 1024..1028).
__device__ float g_gx[(size_t)T_ * B_ * G_ + 4096];

// ---- f32x2 packed helpers (sm_103a FFMA2) ----
__device__ __forceinline__ void fma2(ull& acc, ull a, ull b) {
    asm("fma.rn.f32x2 %0, %1, %2, %0;" : "+l"(acc) : "l"(a), "l"(b));
}
__device__ __forceinline__ ull add2(ull a, ull b) {
    ull r;
    asm("add.rn.f32x2 %0, %1, %2;" : "=l"(r) : "l"(a), "l"(b));
    return r;
}
__device__ __forceinline__ ull pk2(float x, float y) {
    ull r;
    asm("mov.b64 %0, {%1, %2};" : "=l"(r) : "f"(x), "f"(y));
    return r;
}
__device__ __forceinline__ float rsum(ull v) {
    float2 r;
    asm("mov.b64 {%0, %1}, %2;" : "=f"(r.x), "=f"(r.y) : "l"(v));
    return r.x + r.y;
}

// ---- fast activations: single-MUFU ex2 / rcp ----
__device__ __forceinline__ float fex2(float x) {
    float r;
    asm("ex2.approx.f32 %0, %1;" : "=f"(r) : "f"(x));
    return r;
}
__device__ __forceinline__ float frcp(float x) {
    float r;
    asm("rcp.approx.f32 %0, %1;" : "=f"(r) : "f"(x));
    return r;
}
#define LOG2E  1.4426950408889634f
__device__ __forceinline__ float sigf(float x) {
    return frcp(1.0f + fex2(-LOG2E * x));
}
__device__ __forceinline__ float tanh_f(float x) {
    return 2.0f * frcp(1.0f + fex2(-2.0f * LOG2E * x)) - 1.0f;
}

// ============================================================================
// Kernel 1: gx[t][b][g] = b_ih0[g] + b_hh0[g] + x[b,t,:] . w_ih0[g,:]
// ============================================================================
#define TT 128
__global__ __launch_bounds__(256, 4)
void xgate_kernel(const float* __restrict__ x,
                  const float* __restrict__ w_ih0,
                  const float* __restrict__ b_ih0,
                  const float* __restrict__ b_hh0) {
    __shared__ __align__(16) float xs[TT][I_];   // 8 KB
    const int b   = blockIdx.y;
    const int t0  = blockIdx.x * TT;
    const int tid = threadIdx.x;

    const float4* src = (const float4*)(x + ((size_t)b * T_ + t0) * I_);
    ((float4*)xs)[tid]       = src[tid];
    ((float4*)xs)[tid + 256] = src[tid + 256];
    __syncthreads();

    if (tid < G_) {
        ull w[8];
        #pragma unroll
        for (int k2 = 0; k2 < 8; k2++)
            w[k2] = pk2(__ldg(&w_ih0[tid * I_ + 2 * k2]),
                        __ldg(&w_ih0[tid * I_ + 2 * k2 + 1]));
        const float bias = __ldg(&b_ih0[tid]) + __ldg(&b_hh0[tid]);
        for (int tt = 0; tt < TT; tt++) {
            ull acc = pk2(bias, 0.0f);
            #pragma unroll
            for (int q = 0; q < 4; q++) {
                const ulonglong2 v = *(const ulonglong2*)&xs[tt][4 * q];
                fma2(acc, w[2 * q],     v.x);
                fma2(acc, w[2 * q + 1], v.y);
            }
            g_gx[((size_t)(t0 + tt) * B_ + b) * G_ + tid] = rsum(acc);
        }
    }
}

// ============================================================================
// Kernel 2: fused 2-layer LSTM recurrence + FC head. 384 threads, 6 sections.
// Section s = mat*2 + kh (mat: 0=Whh0.h1(+gx), 1=Wih1.h1(+bias2), 2=Whh1.h2).
// Thread (mat, kh, j<50) computes partial dots of gates {j,50+j,100+j,150+j}
// (= i,f,g,o of hidden unit j) over K-half kh (floats 0-23 / 24-51).
// Each broadcast h-quad LDS.128 feeds 8 FFMA2 (4 gates x f32x2) -> crossbar
// traffic halved vs round 10. Partials stored as float4 {i,f,g,o}; combine
// sums 2 (L1) or 4 (L2) float4s. gx/bias2 folded into partial inits.
// ============================================================================
__global__ __launch_bounds__(NTH, 1)
void fused_lstm_kernel(const float* __restrict__ w_hh0,  // [G, H]
                       const float* __restrict__ w_ih1,  // [G, H]
                       const float* __restrict__ w_hh1,  // [G, H]
                       const float* __restrict__ b_ih1,
                       const float* __restrict__ b_hh1,
                       const float* __restrict__ fc1_w,  // [FC, H]
                       const float* __restrict__ fc1_b,
                       const float* __restrict__ fc2_w,  // [1, FC]
                       const float* __restrict__ fc2_b,
                       float* __restrict__ out)          // [B, 1]
{
    __shared__ __align__(16) float hx[2][NB][52];     // [0]=h1, [1]=h2 (padded)
    __shared__ __align__(16) float4 p[3][2][NB][H_];  // partials {i,f,g,o}

    const int tid  = threadIdx.x;
    const int row0 = blockIdx.x * NB;
    const int sec  = tid >> 6;            // 0..5
    const int mat  = sec >> 1;            // 0/1/2
    const int kh   = sec & 1;             // K-half
    const int j    = tid & 63;            // unit index
    const bool isG = (j < H_);

    // ---- weights: 4 gate rows (i,f,g,o of unit j), this thread's K-half ----
    // kh0: chunks 0..11 (floats 0-23); kh1: chunks 12..25 (floats 24-51).
    ull w0[4][12], w1[4][14];
    if (isG) {
        const float* wm = (mat == 0) ? w_hh0 : (mat == 1) ? w_ih1 : w_hh1;
        if (kh == 0) {
            #pragma unroll
            for (int c = 0; c < 4; c++) {
                const int g = c * H_ + j;
                #pragma unroll
                for (int k2 = 0; k2 < 12; k2++)
                    w0[c][k2] = pk2(__ldg(&wm[g * H_ + 2 * k2]),
                                    __ldg(&wm[g * H_ + 2 * k2 + 1]));
            }
        } else {
            #pragma unroll
            for (int c = 0; c < 4; c++) {
                const int g = c * H_ + j;
                #pragma unroll
                for (int k2 = 12; k2 < 26; k2++) {
                    float a0 = (2 * k2     < H_) ? __ldg(&wm[g * H_ + 2 * k2])     : 0.0f;
                    float a1 = (2 * k2 + 1 < H_) ? __ldg(&wm[g * H_ + 2 * k2 + 1]) : 0.0f;
                    w1[c][k2 - 12] = pk2(a0, a1);
                }
            }
        }
    }

    // ---- per-row accumulator init values (2 classes per thread) ----
    // G0: gx classes (kh0 -> i,f ; kh1 -> g,o), refreshed per iter.
    // G1: bias2 (same classes), constant. G2: zero.
    const int c0 = 2 * kh;                 // first class this thread initializes
    float2 iniv[NB];
    if (isG && mat == 1) {
        const float b0v = __ldg(&b_ih1[c0 * H_ + j])       + __ldg(&b_hh1[c0 * H_ + j]);
        const float b1v = __ldg(&b_ih1[(c0 + 1) * H_ + j]) + __ldg(&b_hh1[(c0 + 1) * H_ + j]);
        #pragma unroll
        for (int r = 0; r < NB; r++) iniv[r] = make_float2(b0v, b1v);
    } else {
        #pragma unroll
        for (int r = 0; r < NB; r++) iniv[r] = make_float2(0.0f, 0.0f);
    }
    if (isG && mat == 0) {   // gx for t=0
        #pragma unroll
        for (int r = 0; r < NB; r++) {
            const size_t base = (size_t)(row0 + r) * G_;
            iniv[r] = make_float2(__ldg(&g_gx[base + c0 * H_ + j]),
                                  __ldg(&g_gx[base + (c0 + 1) * H_ + j]));
        }
    }

    // ---- zero h buffers (pads must stay 0) ----
    for (int k = tid; k < 2 * NB * 52; k += NTH) ((float*)hx)[k] = 0.0f;

    // ---- combine ownership: cells tid and tid+384 (if < 700) ----
    float c_st[2] = {0.0f, 0.0f};
    int   cr[2], cj[2], hoff[2];
    bool  cl2[2];
    const bool has2 = (tid < NCELL - NTH);   // tid < 316
    #pragma unroll
    for (int k = 0; k < 2; k++) {
        const int cell = tid + k * NTH;
        const int c = (cell < NCELL) ? cell : 0;
        cl2[k] = (c >= NC1);
        const int rem = cl2[k] ? c - NC1 : c;
        cr[k] = rem / H_;
        cj[k] = rem - cr[k] * H_;
        hoff[k] = (cl2[k] ? NB * 52 : 0) + cr[k] * 52 + cj[k];
    }
    __syncthreads();

    for (int it = 0; it <= T_; it++) {
        // ---- gate phase ----
        if (isG) {
            const int hs = (mat == 2) ? 1 : 0;

            // G0: prefetch next iter's gx while computing
            float2 gxn[NB];
            const bool pf = (mat == 0) && (it + 1 < T_);
            if (pf) {
                #pragma unroll
                for (int r = 0; r < NB; r++) {
                    const size_t base = ((size_t)(it + 1) * B_ + row0 + r) * G_;
                    gxn[r] = make_float2(__ldg(&g_gx[base + c0 * H_ + j]),
                                         __ldg(&g_gx[base + (c0 + 1) * H_ + j]));
                }
            }

            #pragma unroll
            for (int r = 0; r < NB; r++) {
                ull e[4], o[4];
                #pragma unroll
                for (int c = 0; c < 4; c++) { e[c] = 0ull; o[c] = 0ull; }
                e[c0]     = pk2(iniv[r].x, 0.0f);
                e[c0 + 1] = pk2(iniv[r].y, 0.0f);

                if (kh == 0) {
                    ulonglong2 v[6];
                    #pragma unroll
                    for (int q = 0; q < 6; q++)
                        v[q] = *(const ulonglong2*)&hx[hs][r][4 * q];
                    #pragma unroll
                    for (int q = 0; q < 6; q++) {
                        #pragma unroll
                        for (int c = 0; c < 4; c++) {
                            fma2(e[c], w0[c][2 * q],     v[q].x);
                            fma2(o[c], w0[c][2 * q + 1], v[q].y);
                        }
                    }
                } else {
                    ulonglong2 v[7];
                    #pragma unroll
                    for (int q = 0; q < 7; q++)
                        v[q] = *(const ulonglong2*)&hx[hs][r][4 * (q + 6)];
                    #pragma unroll
                    for (int q = 0; q < 7; q++) {
                        #pragma unroll
                        for (int c = 0; c < 4; c++) {
                            fma2(e[c], w1[c][2 * q],     v[q].x);
                            fma2(o[c], w1[c][2 * q + 1], v[q].y);
                        }
                    }
                }
                p[mat][kh][r][j] = make_float4(rsum(add2(e[0], o[0])),
                                               rsum(add2(e[1], o[1])),
                                               rsum(add2(e[2], o[2])),
                                               rsum(add2(e[3], o[3])));
            }

            if (pf) {
                #pragma unroll
                for (int r = 0; r < NB; r++) iniv[r] = gxn[r];
            }
        }
        __syncthreads();

        // ---- combine: 1-2 cells per thread (float4 partial sums) ----
        #pragma unroll
        for (int k = 0; k < 2; k++) {
            const bool own = (k == 0) || has2;
            if (own) {
                const bool act = cl2[k] ? (it >= 1) : (it < T_);
                if (act) {
                    const int r = cr[k], jj = cj[k];
                    float4 gsum;
                    if (cl2[k]) {
                        const float4 a = p[1][0][r][jj];
                        const float4 b = p[1][1][r][jj];
                        const float4 c = p[2][0][r][jj];
                        const float4 d = p[2][1][r][jj];
                        gsum = make_float4(a.x + b.x + c.x + d.x,
                                           a.y + b.y + c.y + d.y,
                                           a.z + b.z + c.z + d.z,
                                           a.w + b.w + c.w + d.w);
                    } else {
                        const float4 a = p[0][0][r][jj];
                        const float4 b = p[0][1][r][jj];
                        gsum = make_float4(a.x + b.x, a.y + b.y,
                                           a.z + b.z, a.w + b.w);
                    }
                    const float ig = sigf(gsum.x);
                    const float fg = sigf(gsum.y);
                    const float gv = tanh_f(gsum.z);
                    const float og = sigf(gsum.w);
                    c_st[k] = fg * c_st[k] + ig * gv;
                    ((float*)hx)[hoff[k]] = og * tanh_f(c_st[k]);
                }
            }
        }
        __syncthreads();
    }

    // ---- FC head: warps 0-6 each handle one batch row, shfl reduction ----
    const int wid  = tid / 32;
    const int lane = tid - wid * 32;
    if (wid < NB) {
        const int row = row0 + wid;
        if (row < B_) {
            float s = 0.0f;
            #pragma unroll
            for (int uu = 0; uu < 2; uu++) {
                const int u = lane + uu * 32;
                float a = __ldg(&fc1_b[u]);
                #pragma unroll
                for (int k = 0; k < H_; k++)
                    a += __ldg(&fc1_w[u * H_ + k]) * hx[1][wid][k];
                a = fmaxf(a, 0.0f);
                s += a * __ldg(&fc2_w[u]);
            }
            #pragma unroll
            for (int off = 16; off > 0; off >>= 1)
                s += __shfl_down_sync(0xffffffffu, s, off);
            if (lane == 0) out[row] = s + __ldg(&fc2_b[0]);
        }
    }
}

extern "C" void kernel_launch(void* const* d_in, const int* in_sizes, int n_in,
                              void* d_out, int out_size) {
    const float* x     = (const float*)d_in[0];
    const float* w_ih0 = (const float*)d_in[1];
    const float* w_hh0 = (const float*)d_in[2];
    const float* b_ih0 = (const float*)d_in[3];
    const float* b_hh0 = (const float*)d_in[4];
    const float* w_ih1 = (const float*)d_in[5];
    const float* w_hh1 = (const float*)d_in[6];
    const float* b_ih1 = (const float*)d_in[7];
    const float* b_hh1 = (const float*)d_in[8];
    const float* fc1_w = (const float*)d_in[9];
    const float* fc1_b = (const float*)d_in[10];
    const float* fc2_w = (const float*)d_in[11];
    const float* fc2_b = (const float*)d_in[12];
    float* out = (float*)d_out;

    dim3 xg_grid(T_ / TT, B_);
    xgate_kernel<<<xg_grid, 256>>>(x, w_ih0, b_ih0, b_hh0);

    const int grid = (B_ + NB - 1) / NB;   // 147
    fused_lstm_kernel<<<grid, NTH>>>(
        w_hh0, w_ih1, w_hh1, b_ih1, b_hh1,
        fc1_w, fc1_b, fc2_w, fc2_b, out);
}

// round 13
// speedup vs baseline: 1.6989x; 1.6989x over previous
#include <cuda_runtime.h>
#include <cstdint>

// Problem constants
#define B_   1024
#define T_   512
#define I_   16
#define H_   50
#define G_   200      // 4*H
#define FCD  64
#define NB   7        // rows per block -> grid 147, single wave
#define NTH  384      // 12 warps: 6 sections x 64 threads (50 active each)
#define NC1  (NB * H_)        // 350
#define NCELL (2 * NB * H_)   // 700

typedef unsigned long long ull;

// Precomputed bias-folded x-gates for layer 1: [t][b][g] (g = cls*50 + j).
// Padding covers the boundary block's over-read (rows 1024..1028).
__device__ float g_gx[(size_t)T_ * B_ * G_ + 4096];

// ---- f32x2 packed helpers (sm_103a FFMA2) ----
__device__ __forceinline__ void fma2(ull& acc, ull a, ull b) {
    asm("fma.rn.f32x2 %0, %1, %2, %0;" : "+l"(acc) : "l"(a), "l"(b));
}
__device__ __forceinline__ ull pk2(float x, float y) {
    ull r;
    asm("mov.b64 %0, {%1, %2};" : "=l"(r) : "f"(x), "f"(y));
    return r;
}
__device__ __forceinline__ float rsum(ull v) {
    float2 r;
    asm("mov.b64 {%0, %1}, %2;" : "=f"(r.x), "=f"(r.y) : "l"(v));
    return r.x + r.y;
}

// ---- fast activations: single-MUFU ex2 / rcp ----
__device__ __forceinline__ float fex2(float x) {
    float r;
    asm("ex2.approx.f32 %0, %1;" : "=f"(r) : "f"(x));
    return r;
}
__device__ __forceinline__ float frcp(float x) {
    float r;
    asm("rcp.approx.f32 %0, %1;" : "=f"(r) : "f"(x));
    return r;
}
#define LOG2E  1.4426950408889634f
__device__ __forceinline__ float sigf(float x) {
    return frcp(1.0f + fex2(-LOG2E * x));
}
__device__ __forceinline__ float tanh_f(float x) {
    return 2.0f * frcp(1.0f + fex2(-2.0f * LOG2E * x)) - 1.0f;
}

// ============================================================================
// Kernel 1: gx[t][b][g] = b_ih0[g] + b_hh0[g] + x[b,t,:] . w_ih0[g,:]
// ============================================================================
#define TT 128
__global__ __launch_bounds__(256, 4)
void xgate_kernel(const float* __restrict__ x,
                  const float* __restrict__ w_ih0,
                  const float* __restrict__ b_ih0,
                  const float* __restrict__ b_hh0) {
    __shared__ __align__(16) float xs[TT][I_];   // 8 KB
    const int b   = blockIdx.y;
    const int t0  = blockIdx.x * TT;
    const int tid = threadIdx.x;

    const float4* src = (const float4*)(x + ((size_t)b * T_ + t0) * I_);
    ((float4*)xs)[tid]       = src[tid];
    ((float4*)xs)[tid + 256] = src[tid + 256];
    __syncthreads();

    if (tid < G_) {
        ull w[8];
        #pragma unroll
        for (int k2 = 0; k2 < 8; k2++)
            w[k2] = pk2(__ldg(&w_ih0[tid * I_ + 2 * k2]),
                        __ldg(&w_ih0[tid * I_ + 2 * k2 + 1]));
        const float bias = __ldg(&b_ih0[tid]) + __ldg(&b_hh0[tid]);
        for (int tt = 0; tt < TT; tt++) {
            ull acc = pk2(bias, 0.0f);
            #pragma unroll
            for (int q = 0; q < 4; q++) {
                const ulonglong2 v = *(const ulonglong2*)&xs[tt][4 * q];
                fma2(acc, w[2 * q],     v.x);
                fma2(acc, w[2 * q + 1], v.y);
            }
            g_gx[((size_t)(t0 + tt) * B_ + b) * G_ + tid] = rsum(acc);
        }
    }
}

// ============================================================================
// Kernel 2: fused 2-layer LSTM recurrence + FC head. 384 threads, 6 sections.
// Section s = mat*2 + kh (mat: 0=Whh0.h1(+gx), 1=Wih1.h1(+bias2), 2=Whh1.h2).
// Thread (mat, kh, j<50) computes partial dots of gates {j,50+j,100+j,150+j}
// over 7 h-quads starting at quad 6*kh. SINGLE unified weight array w[4][14]
// (zero-padded outside this thread's K-half) so ptxas allocates ONE array --
// round 12's dual w0/w1 arrays forced 208 weight regs and spilled to local.
// Each broadcast h-quad LDS.128 feeds 8 FFMA2.
// ============================================================================
__global__ __launch_bounds__(NTH, 1)
void fused_lstm_kernel(const float* __restrict__ w_hh0,  // [G, H]
                       const float* __restrict__ w_ih1,  // [G, H]
                       const float* __restrict__ w_hh1,  // [G, H]
                       const float* __restrict__ b_ih1,
                       const float* __restrict__ b_hh1,
                       const float* __restrict__ fc1_w,  // [FC, H]
                       const float* __restrict__ fc1_b,
                       const float* __restrict__ fc2_w,  // [1, FC]
                       const float* __restrict__ fc2_b,
                       float* __restrict__ out)          // [B, 1]
{
    __shared__ __align__(16) float hx[2][NB][56];     // [0]=h1, [1]=h2 (padded to 56)
    __shared__ __align__(16) float4 p[3][2][NB][H_];  // partials {i,f,g,o}

    const int tid  = threadIdx.x;
    const int row0 = blockIdx.x * NB;
    const int sec  = tid >> 6;            // 0..5
    const int mat  = sec >> 1;            // 0/1/2
    const int kh   = sec & 1;             // K-half
    const int j    = tid & 63;            // unit index
    const bool isG = (j < H_);
    const int qbase = 6 * kh;             // first h-quad this thread reads

    // ---- weights: 4 gate rows (i,f,g,o of unit j), unified 14-chunk array ----
    // logical chunk for w[c][k2] is (12*kh + k2); zero outside this K-half's
    // ownership (kh0 owns chunks 0..11; kh1 owns 12..25) or past H.
    ull w[4][14];
    if (isG) {
        const float* wm = (mat == 0) ? w_hh0 : (mat == 1) ? w_ih1 : w_hh1;
        #pragma unroll
        for (int c = 0; c < 4; c++) {
            const int g = c * H_ + j;
            #pragma unroll
            for (int k2 = 0; k2 < 14; k2++) {
                const int ch = 12 * kh + k2;
                const bool own = kh ? (ch >= 12 && ch < 26) : (ch < 12);
                float a0 = (own && 2 * ch     < H_) ? __ldg(&wm[g * H_ + 2 * ch])     : 0.0f;
                float a1 = (own && 2 * ch + 1 < H_) ? __ldg(&wm[g * H_ + 2 * ch + 1]) : 0.0f;
                w[c][k2] = pk2(a0, a1);
            }
        }
    }

    // ---- per-row accumulator init values (2 classes per thread) ----
    const int c0 = 2 * kh;
    float2 iniv[NB];
    if (isG && mat == 1) {
        const float b0v = __ldg(&b_ih1[c0 * H_ + j])       + __ldg(&b_hh1[c0 * H_ + j]);
        const float b1v = __ldg(&b_ih1[(c0 + 1) * H_ + j]) + __ldg(&b_hh1[(c0 + 1) * H_ + j]);
        #pragma unroll
        for (int r = 0; r < NB; r++) iniv[r] = make_float2(b0v, b1v);
    } else {
        #pragma unroll
        for (int r = 0; r < NB; r++) iniv[r] = make_float2(0.0f, 0.0f);
    }
    if (isG && mat == 0) {   // gx for t=0
        #pragma unroll
        for (int r = 0; r < NB; r++) {
            const size_t base = (size_t)(row0 + r) * G_;
            iniv[r] = make_float2(__ldg(&g_gx[base + c0 * H_ + j]),
                                  __ldg(&g_gx[base + (c0 + 1) * H_ + j]));
        }
    }

    // ---- zero h buffers (pads must stay 0) ----
    for (int k = tid; k < 2 * NB * 56; k += NTH) ((float*)hx)[k] = 0.0f;

    // ---- combine ownership: cells tid and tid+384 (if < 700) ----
    float c_st[2] = {0.0f, 0.0f};
    int   cr[2], cj[2], hoff[2];
    bool  cl2[2];
    const bool has2 = (tid < NCELL - NTH);   // tid < 316
    #pragma unroll
    for (int k = 0; k < 2; k++) {
        const int cell = tid + k * NTH;
        const int c = (cell < NCELL) ? cell : 0;
        cl2[k] = (c >= NC1);
        const int rem = cl2[k] ? c - NC1 : c;
        cr[k] = rem / H_;
        cj[k] = rem - cr[k] * H_;
        hoff[k] = (cl2[k] ? NB * 56 : 0) + cr[k] * 56 + cj[k];
    }
    __syncthreads();

    for (int it = 0; it <= T_; it++) {
        // ---- gate phase ----
        if (isG) {
            const int hs = (mat == 2) ? 1 : 0;

            // G0: prefetch next iter's gx while computing
            float2 gxn[NB];
            const bool pf = (mat == 0) && (it + 1 < T_);
            if (pf) {
                #pragma unroll
                for (int r = 0; r < NB; r++) {
                    const size_t base = ((size_t)(it + 1) * B_ + row0 + r) * G_;
                    gxn[r] = make_float2(__ldg(&g_gx[base + c0 * H_ + j]),
                                         __ldg(&g_gx[base + (c0 + 1) * H_ + j]));
                }
            }

            #pragma unroll
            for (int r = 0; r < NB; r++) {
                ull a[4];
                a[0] = 0ull; a[1] = 0ull; a[2] = 0ull; a[3] = 0ull;
                a[c0]     = pk2(iniv[r].x, 0.0f);
                a[c0 + 1] = pk2(iniv[r].y, 0.0f);

                // batch 1: quads qbase .. qbase+3
                ulonglong2 v[4];
                #pragma unroll
                for (int q = 0; q < 4; q++)
                    v[q] = *(const ulonglong2*)&hx[hs][r][4 * (qbase + q)];
                #pragma unroll
                for (int q = 0; q < 4; q++) {
                    #pragma unroll
                    for (int c = 0; c < 4; c++) {
                        fma2(a[c], w[c][2 * q],     v[q].x);
                        fma2(a[c], w[c][2 * q + 1], v[q].y);
                    }
                }
                // batch 2: quads qbase+4 .. qbase+6
                #pragma unroll
                for (int q = 0; q < 3; q++)
                    v[q] = *(const ulonglong2*)&hx[hs][r][4 * (qbase + 4 + q)];
                #pragma unroll
                for (int q = 0; q < 3; q++) {
                    #pragma unroll
                    for (int c = 0; c < 4; c++) {
                        fma2(a[c], w[c][2 * (q + 4)],     v[q].x);
                        fma2(a[c], w[c][2 * (q + 4) + 1], v[q].y);
                    }
                }
                p[mat][kh][r][j] = make_float4(rsum(a[0]), rsum(a[1]),
                                               rsum(a[2]), rsum(a[3]));
            }

            if (pf) {
                #pragma unroll
                for (int r = 0; r < NB; r++) iniv[r] = gxn[r];
            }
        }
        __syncthreads();

        // ---- combine: 1-2 cells per thread (float4 partial sums) ----
        #pragma unroll
        for (int k = 0; k < 2; k++) {
            const bool own = (k == 0) || has2;
            if (own) {
                const bool act = cl2[k] ? (it >= 1) : (it < T_);
                if (act) {
                    const int r = cr[k], jj = cj[k];
                    float4 gsum;
                    if (cl2[k]) {
                        const float4 a = p[1][0][r][jj];
                        const float4 b = p[1][1][r][jj];
                        const float4 c = p[2][0][r][jj];
                        const float4 d = p[2][1][r][jj];
                        gsum = make_float4(a.x + b.x + c.x + d.x,
                                           a.y + b.y + c.y + d.y,
                                           a.z + b.z + c.z + d.z,
                                           a.w + b.w + c.w + d.w);
                    } else {
                        const float4 a = p[0][0][r][jj];
                        const float4 b = p[0][1][r][jj];
                        gsum = make_float4(a.x + b.x, a.y + b.y,
                                           a.z + b.z, a.w + b.w);
                    }
                    const float ig = sigf(gsum.x);
                    const float fg = sigf(gsum.y);
                    const float gv = tanh_f(gsum.z);
                    const float og = sigf(gsum.w);
                    c_st[k] = fg * c_st[k] + ig * gv;
                    ((float*)hx)[hoff[k]] = og * tanh_f(c_st[k]);
                }
            }
        }
        __syncthreads();
    }

    // ---- FC head: warps 0-6 each handle one batch row, shfl reduction ----
    const int wid  = tid / 32;
    const int lane = tid - wid * 32;
    if (wid < NB) {
        const int row = row0 + wid;
        if (row < B_) {
            float s = 0.0f;
            #pragma unroll
            for (int uu = 0; uu < 2; uu++) {
                const int u = lane + uu * 32;
                float a = __ldg(&fc1_b[u]);
                #pragma unroll
                for (int k = 0; k < H_; k++)
                    a += __ldg(&fc1_w[u * H_ + k]) * hx[1][wid][k];
                a = fmaxf(a, 0.0f);
                s += a * __ldg(&fc2_w[u]);
            }
            #pragma unroll
            for (int off = 16; off > 0; off >>= 1)
                s += __shfl_down_sync(0xffffffffu, s, off);
            if (lane == 0) out[row] = s + __ldg(&fc2_b[0]);
        }
    }
}

extern "C" void kernel_launch(void* const* d_in, const int* in_sizes, int n_in,
                              void* d_out, int out_size) {
    const float* x     = (const float*)d_in[0];
    const float* w_ih0 = (const float*)d_in[1];
    const float* w_hh0 = (const float*)d_in[2];
    const float* b_ih0 = (const float*)d_in[3];
    const float* b_hh0 = (const float*)d_in[4];
    const float* w_ih1 = (const float*)d_in[5];
    const float* w_hh1 = (const float*)d_in[6];
    const float* b_ih1 = (const float*)d_in[7];
    const float* b_hh1 = (const float*)d_in[8];
    const float* fc1_w = (const float*)d_in[9];
    const float* fc1_b = (const float*)d_in[10];
    const float* fc2_w = (const float*)d_in[11];
    const float* fc2_b = (const float*)d_in[12];
    float* out = (float*)d_out;

    dim3 xg_grid(T_ / TT, B_);
    xgate_kernel<<<xg_grid, 256>>>(x, w_ih0, b_ih0, b_hh0);

    const int grid = (B_ + NB - 1) / NB;   // 147
    fused_lstm_kernel<<<grid, NTH>>>(
        w_hh0, w_ih1, w_hh1, b_ih1, b_hh1,
        fc1_w, fc1_b, fc2_w, fc2_b, out);
}

// round 14
// speedup vs baseline: 1.7508x; 1.0305x over previous
#include <cuda_runtime.h>
#include <cstdint>

// Problem constants
#define B_   1024
#define T_   512
#define I_   16
#define H_   50
#define G_   200      // 4*H
#define FCD  64
#define NB   7        // rows per block -> grid 147, single wave
#define NTH  384      // 12 warps: 6 sections x 64 threads (50 active each)
#define NC1  (NB * H_)        // 350
#define NCELL (2 * NB * H_)   // 700

typedef unsigned long long ull;

// Precomputed bias-folded x-gates for layer 1: [t][b][g] (g = cls*50 + j).
// Padding covers the boundary block's over-read (rows 1024..1028).
__device__ float g_gx[(size_t)T_ * B_ * G_ + 4096];

// ---- f32x2 packed helpers (sm_103a FFMA2) ----
__device__ __forceinline__ void fma2(ull& acc, ull a, ull b) {
    asm("fma.rn.f32x2 %0, %1, %2, %0;" : "+l"(acc) : "l"(a), "l"(b));
}
__device__ __forceinline__ ull pk2(float x, float y) {
    ull r;
    asm("mov.b64 %0, {%1, %2};" : "=l"(r) : "f"(x), "f"(y));
    return r;
}
__device__ __forceinline__ float rsum(ull v) {
    float2 r;
    asm("mov.b64 {%0, %1}, %2;" : "=f"(r.x), "=f"(r.y) : "l"(v));
    return r.x + r.y;
}

// ---- fast activations: single-MUFU ex2 / rcp ----
__device__ __forceinline__ float fex2(float x) {
    float r;
    asm("ex2.approx.f32 %0, %1;" : "=f"(r) : "f"(x));
    return r;
}
__device__ __forceinline__ float frcp(float x) {
    float r;
    asm("rcp.approx.f32 %0, %1;" : "=f"(r) : "f"(x));
    return r;
}
#define LOG2E  1.4426950408889634f
__device__ __forceinline__ float sigf(float x) {
    return frcp(1.0f + fex2(-LOG2E * x));
}
__device__ __forceinline__ float tanh_f(float x) {
    return 2.0f * frcp(1.0f + fex2(-2.0f * LOG2E * x)) - 1.0f;
}

// ============================================================================
// Kernel 1: gx[t][b][g] = b_ih0[g] + b_hh0[g] + x[b,t,:] . w_ih0[g,:]
// ============================================================================
#define TT 128
__global__ __launch_bounds__(256, 4)
void xgate_kernel(const float* __restrict__ x,
                  const float* __restrict__ w_ih0,
                  const float* __restrict__ b_ih0,
                  const float* __restrict__ b_hh0) {
    __shared__ __align__(16) float xs[TT][I_];   // 8 KB
    const int b   = blockIdx.y;
    const int t0  = blockIdx.x * TT;
    const int tid = threadIdx.x;

    const float4* src = (const float4*)(x + ((size_t)b * T_ + t0) * I_);
    ((float4*)xs)[tid]       = src[tid];
    ((float4*)xs)[tid + 256] = src[tid + 256];
    __syncthreads();

    if (tid < G_) {
        ull w[8];
        #pragma unroll
        for (int k2 = 0; k2 < 8; k2++)
            w[k2] = pk2(__ldg(&w_ih0[tid * I_ + 2 * k2]),
                        __ldg(&w_ih0[tid * I_ + 2 * k2 + 1]));
        const float bias = __ldg(&b_ih0[tid]) + __ldg(&b_hh0[tid]);
        for (int tt = 0; tt < TT; tt++) {
            ull acc = pk2(bias, 0.0f);
            #pragma unroll
            for (int q = 0; q < 4; q++) {
                const ulonglong2 v = *(const ulonglong2*)&xs[tt][4 * q];
                fma2(acc, w[2 * q],     v.x);
                fma2(acc, w[2 * q + 1], v.y);
            }
            g_gx[((size_t)(t0 + tt) * B_ + b) * G_ + tid] = rsum(acc);
        }
    }
}

// ============================================================================
// Kernel 2: fused 2-layer LSTM recurrence + FC head. 384 threads, 6 sections.
// Section s = mat*2 + kh (mat: 0=Whh0.h1(+gx), 1=Wih1.h1(+bias2), 2=Whh1.h2).
// Thread (mat, kh, j<50) computes partial dots of gates {j,50+j,100+j,150+j}
// over 7 h-quads starting at quad 6*kh, weights in a unified w[4][14] array.
// Each broadcast h-quad LDS.128 feeds 8 FFMA2 (crossbar halved vs 2-gate map).
// CRITICAL FIX vs rounds 12/13: accumulator init uses CONSTANT indices only
// (kh-branch); the previous a[c0] dynamic index demoted the accumulators to
// local memory (the L2=44% spill traffic those rounds showed).
// ============================================================================
__global__ __launch_bounds__(NTH, 1)
void fused_lstm_kernel(const float* __restrict__ w_hh0,  // [G, H]
                       const float* __restrict__ w_ih1,  // [G, H]
                       const float* __restrict__ w_hh1,  // [G, H]
                       const float* __restrict__ b_ih1,
                       const float* __restrict__ b_hh1,
                       const float* __restrict__ fc1_w,  // [FC, H]
                       const float* __restrict__ fc1_b,
                       const float* __restrict__ fc2_w,  // [1, FC]
                       const float* __restrict__ fc2_b,
                       float* __restrict__ out)          // [B, 1]
{
    __shared__ __align__(16) float hx[2][NB][56];     // [0]=h1, [1]=h2 (padded)
    __shared__ __align__(16) float4 p[3][2][NB][H_];  // partials {i,f,g,o}

    const int tid  = threadIdx.x;
    const int row0 = blockIdx.x * NB;
    const int sec  = tid >> 6;            // 0..5
    const int mat  = sec >> 1;            // 0/1/2
    const int kh   = sec & 1;             // K-half
    const int j    = tid & 63;            // unit index
    const bool isG = (j < H_);
    const int qbase = 6 * kh;             // first h-quad this thread reads

    // ---- weights: 4 gate rows (i,f,g,o of unit j), unified 14-chunk array ----
    ull w[4][14];
    if (isG) {
        const float* wm = (mat == 0) ? w_hh0 : (mat == 1) ? w_ih1 : w_hh1;
        #pragma unroll
        for (int c = 0; c < 4; c++) {
            const int g = c * H_ + j;
            #pragma unroll
            for (int k2 = 0; k2 < 14; k2++) {
                const int ch = 12 * kh + k2;
                const bool own = kh ? (ch >= 12 && ch < 26) : (ch < 12);
                float a0 = (own && 2 * ch     < H_) ? __ldg(&wm[g * H_ + 2 * ch])     : 0.0f;
                float a1 = (own && 2 * ch + 1 < H_) ? __ldg(&wm[g * H_ + 2 * ch + 1]) : 0.0f;
                w[c][k2] = pk2(a0, a1);
            }
        }
    }

    // ---- per-row accumulator init values (2 classes per thread) ----
    // classes c0=2*kh, c0+1: G0 -> gx (refreshed per iter), G1 -> bias2, G2 -> 0
    const int c0 = 2 * kh;
    float2 iniv[NB];
    if (isG && mat == 1) {
        const float b0v = __ldg(&b_ih1[c0 * H_ + j])       + __ldg(&b_hh1[c0 * H_ + j]);
        const float b1v = __ldg(&b_ih1[(c0 + 1) * H_ + j]) + __ldg(&b_hh1[(c0 + 1) * H_ + j]);
        #pragma unroll
        for (int r = 0; r < NB; r++) iniv[r] = make_float2(b0v, b1v);
    } else {
        #pragma unroll
        for (int r = 0; r < NB; r++) iniv[r] = make_float2(0.0f, 0.0f);
    }
    if (isG && mat == 0) {   // gx for t=0
        #pragma unroll
        for (int r = 0; r < NB; r++) {
            const size_t base = (size_t)(row0 + r) * G_;
            iniv[r] = make_float2(__ldg(&g_gx[base + c0 * H_ + j]),
                                  __ldg(&g_gx[base + (c0 + 1) * H_ + j]));
        }
    }

    // ---- zero h buffers (pads must stay 0) ----
    for (int k = tid; k < 2 * NB * 56; k += NTH) ((float*)hx)[k] = 0.0f;

    // ---- combine ownership: cells tid and tid+384 (if < 700) ----
    float c_st[2] = {0.0f, 0.0f};
    int   cr[2], cj[2], hoff[2];
    bool  cl2[2];
    const bool has2 = (tid < NCELL - NTH);   // tid < 316
    #pragma unroll
    for (int k = 0; k < 2; k++) {
        const int cell = tid + k * NTH;
        const int c = (cell < NCELL) ? cell : 0;
        cl2[k] = (c >= NC1);
        const int rem = cl2[k] ? c - NC1 : c;
        cr[k] = rem / H_;
        cj[k] = rem - cr[k] * H_;
        hoff[k] = (cl2[k] ? NB * 56 : 0) + cr[k] * 56 + cj[k];
    }
    __syncthreads();

    for (int it = 0; it <= T_; it++) {
        // ---- gate phase ----
        if (isG) {
            const int hs = (mat == 2) ? 1 : 0;

            // G0: prefetch next iter's gx while computing
            float2 gxn[NB];
            const bool pf = (mat == 0) && (it + 1 < T_);
            if (pf) {
                #pragma unroll
                for (int r = 0; r < NB; r++) {
                    const size_t base = ((size_t)(it + 1) * B_ + row0 + r) * G_;
                    gxn[r] = make_float2(__ldg(&g_gx[base + c0 * H_ + j]),
                                         __ldg(&g_gx[base + (c0 + 1) * H_ + j]));
                }
            }

            #pragma unroll
            for (int r = 0; r < NB; r++) {
                // CONSTANT-index accumulator init (kh is warp-uniform)
                ull a[4];
                if (kh == 0) {
                    a[0] = pk2(iniv[r].x, 0.0f);
                    a[1] = pk2(iniv[r].y, 0.0f);
                    a[2] = 0ull;
                    a[3] = 0ull;
                } else {
                    a[0] = 0ull;
                    a[1] = 0ull;
                    a[2] = pk2(iniv[r].x, 0.0f);
                    a[3] = pk2(iniv[r].y, 0.0f);
                }

                // batch 1: quads qbase .. qbase+3
                ulonglong2 v[4];
                #pragma unroll
                for (int q = 0; q < 4; q++)
                    v[q] = *(const ulonglong2*)&hx[hs][r][4 * (qbase + q)];
                #pragma unroll
                for (int q = 0; q < 4; q++) {
                    #pragma unroll
                    for (int c = 0; c < 4; c++) {
                        fma2(a[c], w[c][2 * q],     v[q].x);
                        fma2(a[c], w[c][2 * q + 1], v[q].y);
                    }
                }
                // batch 2: quads qbase+4 .. qbase+6
                #pragma unroll
                for (int q = 0; q < 3; q++)
                    v[q] = *(const ulonglong2*)&hx[hs][r][4 * (qbase + 4 + q)];
                #pragma unroll
                for (int q = 0; q < 3; q++) {
                    #pragma unroll
                    for (int c = 0; c < 4; c++) {
                        fma2(a[c], w[c][2 * (q + 4)],     v[q].x);
                        fma2(a[c], w[c][2 * (q + 4) + 1], v[q].y);
                    }
                }
                p[mat][kh][r][j] = make_float4(rsum(a[0]), rsum(a[1]),
                                               rsum(a[2]), rsum(a[3]));
            }

            if (pf) {
                #pragma unroll
                for (int r = 0; r < NB; r++) iniv[r] = gxn[r];
            }
        }
        __syncthreads();

        // ---- combine: 1-2 cells per thread (float4 partial sums) ----
        #pragma unroll
        for (int k = 0; k < 2; k++) {
            const bool own = (k == 0) || has2;
            if (own) {
                const bool act = cl2[k] ? (it >= 1) : (it < T_);
                if (act) {
                    const int r = cr[k], jj = cj[k];
                    float4 gsum;
                    if (cl2[k]) {
                        const float4 a = p[1][0][r][jj];
                        const float4 b = p[1][1][r][jj];
                        const float4 c = p[2][0][r][jj];
                        const float4 d = p[2][1][r][jj];
                        gsum = make_float4(a.x + b.x + c.x + d.x,
                                           a.y + b.y + c.y + d.y,
                                           a.z + b.z + c.z + d.z,
                                           a.w + b.w + c.w + d.w);
                    } else {
                        const float4 a = p[0][0][r][jj];
                        const float4 b = p[0][1][r][jj];
                        gsum = make_float4(a.x + b.x, a.y + b.y,
                                           a.z + b.z, a.w + b.w);
                    }
                    const float ig = sigf(gsum.x);
                    const float fg = sigf(gsum.y);
                    const float gv = tanh_f(gsum.z);
                    const float og = sigf(gsum.w);
                    c_st[k] = fg * c_st[k] + ig * gv;
                    ((float*)hx)[hoff[k]] = og * tanh_f(c_st[k]);
                }
            }
        }
        __syncthreads();
    }

    // ---- FC head: warps 0-6 each handle one batch row, shfl reduction ----
    const int wid  = tid / 32;
    const int lane = tid - wid * 32;
    if (wid < NB) {
        const int row = row0 + wid;
        if (row < B_) {
            float s = 0.0f;
            #pragma unroll
            for (int uu = 0; uu < 2; uu++) {
                const int u = lane + uu * 32;
                float a = __ldg(&fc1_b[u]);
                #pragma unroll
                for (int k = 0; k < H_; k++)
                    a += __ldg(&fc1_w[u * H_ + k]) * hx[1][wid][k];
                a = fmaxf(a, 0.0f);
                s += a * __ldg(&fc2_w[u]);
            }
            #pragma unroll
            for (int off = 16; off > 0; off >>= 1)
                s += __shfl_down_sync(0xffffffffu, s, off);
            if (lane == 0) out[row] = s + __ldg(&fc2_b[0]);
        }
    }
}

extern "C" void kernel_launch(void* const* d_in, const int* in_sizes, int n_in,
                              void* d_out, int out_size) {
    const float* x     = (const float*)d_in[0];
    const float* w_ih0 = (const float*)d_in[1];
    const float* w_hh0 = (const float*)d_in[2];
    const float* b_ih0 = (const float*)d_in[3];
    const float* b_hh0 = (const float*)d_in[4];
    const float* w_ih1 = (const float*)d_in[5];
    const float* w_hh1 = (const float*)d_in[6];
    const float* b_ih1 = (const float*)d_in[7];
    const float* b_hh1 = (const float*)d_in[8];
    const float* fc1_w = (const float*)d_in[9];
    const float* fc1_b = (const float*)d_in[10];
    const float* fc2_w = (const float*)d_in[11];
    const float* fc2_b = (const float*)d_in[12];
    float* out = (float*)d_out;

    dim3 xg_grid(T_ / TT, B_);
    xgate_kernel<<<xg_grid, 256>>>(x, w_ih0, b_ih0, b_hh0);

    const int grid = (B_ + NB - 1) / NB;   // 147
    fused_lstm_kernel<<<grid, NTH>>>(
        w_hh0, w_ih1, w_hh1, b_ih1, b_hh1,
        fc1_w, fc1_b, fc2_w, fc2_b, out);
}